// round 6
// baseline (speedup 1.0000x reference)
#include <cuda_runtime.h>
#include <stdint.h>
#include <math.h>

#define NB 128      // batch
#define NTT 32      // timesteps
#define NV 32000    // vocab
#define NE 128      // embed dim
#define NH 256      // hidden
#define NF 2048     // feature dim
#define NG 1024     // 4*H (gates)
#define LDW (NE + NF)   // W_ih row stride = 2176
#define NCTA 128    // persistent-kernel grid

// ---------------- scratch (device globals; no allocation allowed) ------------
__device__ float g_embed[NTT * NB * NE];            // [t][b][e]
__device__ float g_gembT[NG * NTT * NB];            // [j][t*NB+b]  transposed gates_emb
__device__ float g_gbaseT[NG * NB];                 // [j][b]       transposed gates_base (+biases)
__device__ float g_bpart[8 * NG * NB];              // K-split partials for gates_base
__device__ float g_hbuf[(NTT + 1) * NH * NB];       // h ping chain: buffer t = h at step t (transposed [h][b])
__device__ float g_cT[NH * NB];                     // c transposed [h][b]
__device__ float g_Hall[NTT * NB * NH];             // [t][b][h] for fc
__device__ float g_initpart[2 * 8 * NB * NH];       // K-split partials for h0/c0
__device__ unsigned g_bar;                          // grid barrier counter

// ---------------- helpers ----------------------------------------------------
__device__ __forceinline__ uint32_t f2tf32(float x) {
    uint32_t u;
    asm("cvt.rna.tf32.f32 %0, %1;" : "=r"(u) : "f"(x));
    return u;
}

__device__ __forceinline__ void mma_tf32(float* d, const uint32_t* a, const uint32_t* b) {
    asm volatile(
        "mma.sync.aligned.m16n8k8.row.col.f32.tf32.tf32.f32 "
        "{%0,%1,%2,%3}, {%4,%5,%6,%7}, {%8,%9}, {%0,%1,%2,%3};"
        : "+f"(d[0]), "+f"(d[1]), "+f"(d[2]), "+f"(d[3])
        : "r"(a[0]), "r"(a[1]), "r"(a[2]), "r"(a[3]), "r"(b[0]), "r"(b[1]));
}

// ---------------- gather: g_embed[(t*NB+b)*NE + e] = embeddings[captions[b,t]] ----
__global__ void gather_embed_kernel(const int* __restrict__ captions,
                                    const float* __restrict__ embeddings) {
    int idx = blockIdx.x * blockDim.x + threadIdx.x;
    if (idx >= NTT * NB * NE) return;
    int e = idx % NE;
    int m = idx / NE;          // t*NB + b
    int t = m / NB;
    int b = m % NB;
    int tok = captions[b * NTT + t];
    g_embed[idx] = embeddings[tok * NE + e];
}

__global__ void reset_bar_kernel() { g_bar = 0u; }

// ---------------- init h0/c0: NN gemm with deterministic K-split -------------
__global__ void init_part_kernel(const float* __restrict__ A,   // features (NB, NF)
                                 const float* __restrict__ W,   // (NF, NH)
                                 int mat) {
    __shared__ float As[16][64];
    __shared__ float Bs[16][64];
    int n0 = blockIdx.x * 64;
    int m0 = blockIdx.y * 64;
    int kz = blockIdx.z;
    int tid = threadIdx.x;
    int lm = tid >> 2, lk = (tid & 3) * 4;
    int kr = tid >> 4, n4 = (tid & 15) * 4;
    int tx = tid & 15, ty = tid >> 4;
    float acc[4][4] = {};

    for (int k0 = kz * 256; k0 < kz * 256 + 256; k0 += 16) {
        float4 av = *(const float4*)&A[(size_t)(m0 + lm) * NF + k0 + lk];
        As[lk + 0][lm] = av.x; As[lk + 1][lm] = av.y;
        As[lk + 2][lm] = av.z; As[lk + 3][lm] = av.w;
        float4 bv = *(const float4*)&W[(size_t)(k0 + kr) * NH + n0 + n4];
        *(float4*)&Bs[kr][n4] = bv;
        __syncthreads();
        #pragma unroll
        for (int kk = 0; kk < 16; kk++) {
            float4 a = *(const float4*)&As[kk][ty * 4];
            float4 b = *(const float4*)&Bs[kk][tx * 4];
            float ar[4] = {a.x, a.y, a.z, a.w};
            float br[4] = {b.x, b.y, b.z, b.w};
            #pragma unroll
            for (int i = 0; i < 4; i++)
                #pragma unroll
                for (int j = 0; j < 4; j++)
                    acc[i][j] = fmaf(ar[i], br[j], acc[i][j]);
        }
        __syncthreads();
    }
    float* dst = g_initpart + ((size_t)(mat * 8 + kz) * NB) * NH;
    #pragma unroll
    for (int i = 0; i < 4; i++)
        #pragma unroll
        for (int j = 0; j < 4; j++)
            dst[(size_t)(m0 + ty * 4 + i) * NH + n0 + tx * 4 + j] = acc[i][j];
}

// reduce + transpose: writes h0 into g_hbuf[0] (layout [h][b]) and g_cT [h][b]
__global__ void init_reduce_kernel(const float* __restrict__ bH,
                                   const float* __restrict__ bC) {
    int idx = blockIdx.x * blockDim.x + threadIdx.x;   // NB*NH, partials are [b][h]
    int b = idx >> 8;
    int h = idx & 255;
    float sH = bH[h], sC = bC[h];
    #pragma unroll
    for (int z = 0; z < 8; z++) {
        sH += g_initpart[(size_t)z * NB * NH + idx];
        sC += g_initpart[(size_t)(8 + z) * NB * NH + idx];
    }
    g_hbuf[h * NB + b] = sH;
    g_cT[h * NB + b] = sC;
}

// ---------------- generic NT sgemm: C[M,N] = A(M,K) @ B(N,K)^T ---------------
__global__ void sgemm_nt64(const float* __restrict__ A, int lda,
                           const float* __restrict__ B, int ldb,
                           float* __restrict__ C, int ldc, int K) {
    __shared__ float As[16][64];
    __shared__ float Bs[16][64];
    int m0 = blockIdx.y * 64;
    int n0 = blockIdx.x * 64;
    int tid = threadIdx.x;
    int lm = tid >> 2;
    int lk = (tid & 3) * 4;
    int tx = tid & 15;
    int ty = tid >> 4;
    float acc[4][4] = {};

    for (int k0 = 0; k0 < K; k0 += 16) {
        float4 av = *(const float4*)&A[(size_t)(m0 + lm) * lda + k0 + lk];
        float4 bv = *(const float4*)&B[(size_t)(n0 + lm) * ldb + k0 + lk];
        As[lk + 0][lm] = av.x; As[lk + 1][lm] = av.y;
        As[lk + 2][lm] = av.z; As[lk + 3][lm] = av.w;
        Bs[lk + 0][lm] = bv.x; Bs[lk + 1][lm] = bv.y;
        Bs[lk + 2][lm] = bv.z; Bs[lk + 3][lm] = bv.w;
        __syncthreads();
        #pragma unroll
        for (int kk = 0; kk < 16; kk++) {
            float4 a = *(const float4*)&As[kk][ty * 4];
            float4 b = *(const float4*)&Bs[kk][tx * 4];
            float ar[4] = {a.x, a.y, a.z, a.w};
            float br[4] = {b.x, b.y, b.z, b.w};
            #pragma unroll
            for (int i = 0; i < 4; i++)
                #pragma unroll
                for (int j = 0; j < 4; j++)
                    acc[i][j] = fmaf(ar[i], br[j], acc[i][j]);
        }
        __syncthreads();
    }

    #pragma unroll
    for (int i = 0; i < 4; i++)
        #pragma unroll
        for (int j = 0; j < 4; j++)
            C[(size_t)(m0 + ty * 4 + i) * ldc + n0 + tx * 4 + j] = acc[i][j];
}

// ---------------- gates_base: K-split NT gemm (M=NG rows j, N=NB, K=2048) ----
__global__ void gbase_part_kernel(const float* __restrict__ A,   // W_ih + NE, lda=LDW
                                  const float* __restrict__ B) { // features, ldb=NF
    __shared__ float As[16][64];
    __shared__ float Bs[16][64];
    int n0 = blockIdx.x * 64;   // b
    int m0 = blockIdx.y * 64;   // j
    int kz = blockIdx.z;
    int tid = threadIdx.x;
    int lm = tid >> 2;
    int lk = (tid & 3) * 4;
    int tx = tid & 15;
    int ty = tid >> 4;
    float acc[4][4] = {};

    for (int k0 = kz * 256; k0 < kz * 256 + 256; k0 += 16) {
        float4 av = *(const float4*)&A[(size_t)(m0 + lm) * LDW + k0 + lk];
        float4 bv = *(const float4*)&B[(size_t)(n0 + lm) * NF + k0 + lk];
        As[lk + 0][lm] = av.x; As[lk + 1][lm] = av.y;
        As[lk + 2][lm] = av.z; As[lk + 3][lm] = av.w;
        Bs[lk + 0][lm] = bv.x; Bs[lk + 1][lm] = bv.y;
        Bs[lk + 2][lm] = bv.z; Bs[lk + 3][lm] = bv.w;
        __syncthreads();
        #pragma unroll
        for (int kk = 0; kk < 16; kk++) {
            float4 a = *(const float4*)&As[kk][ty * 4];
            float4 b = *(const float4*)&Bs[kk][tx * 4];
            float ar[4] = {a.x, a.y, a.z, a.w};
            float br[4] = {b.x, b.y, b.z, b.w};
            #pragma unroll
            for (int i = 0; i < 4; i++)
                #pragma unroll
                for (int j = 0; j < 4; j++)
                    acc[i][j] = fmaf(ar[i], br[j], acc[i][j]);
        }
        __syncthreads();
    }
    float* dst = g_bpart + (size_t)kz * NG * NB;
    #pragma unroll
    for (int i = 0; i < 4; i++)
        #pragma unroll
        for (int j = 0; j < 4; j++)
            dst[(size_t)(m0 + ty * 4 + i) * NB + n0 + tx * 4 + j] = acc[i][j];
}

__global__ void gbase_reduce_kernel(const float* __restrict__ bih,
                                    const float* __restrict__ bhh) {
    int idx = blockIdx.x * blockDim.x + threadIdx.x;   // NG*NB
    int j = idx >> 7;
    float s = bih[j] + bhh[j];
    #pragma unroll
    for (int z = 0; z < 8; z++)
        s += g_bpart[(size_t)z * NG * NB + idx];
    g_gbaseT[idx] = s;
}

// ---------------- persistent fused LSTM recurrence ---------------------------
// 128 CTAs x 256 threads, all co-resident. CTA c owns h-indices {2c, 2c+1}
// => 8 gate rows (4 gate types x 2). Warp w: gtype=w>>1, batch-half=w&1,
// computes BOTH rows of its gtype for 64 batches (2 batches/lane via float2,
// 2 W-regs/k => 8 FMA per 8B loaded: smem/L1-balanced).
// h flows through NTT+1 distinct global buffers: every load of buffer t+1 is a
// first-touch L1 line, so plain cached LDG is coherent. Grid barrier per step.
__global__ void __launch_bounds__(256) lstm_persist_kernel(const float* __restrict__ W_hh,
                                                           float* __restrict__ Hall) {
    __shared__ float W_s[8][NH];        // 8 gate rows of W_hh
    __shared__ float gates_s[8][NB];
    const int c = blockIdx.x;
    const int tid = threadIdx.x;
    const int w = tid >> 5, lane = tid & 31;
    const int gtype = w >> 1, bhalf = w & 1;
    const int lr0 = gtype * 2;                 // local row pair
    const int r0 = gtype * NH + 2 * c;         // global gate row pair base

    // load the 8 W_hh rows this CTA needs (warp w loads local row w)
    {
        int gr = (w >> 1) * NH + 2 * c + (w & 1);
        for (int k = lane; k < NH; k += 32)
            W_s[w][k] = W_hh[gr * NH + k];
    }
    // cell-phase mapping; c state lives in a register for all 32 steps
    const int hs = tid >> 7, bb = tid & 127;
    const int hh = 2 * c + hs;
    float c_reg = g_cT[hh * NB + bb];
    __syncthreads();

    const int b0 = bhalf * 64 + 2 * lane;      // 2 consecutive batches per lane
    const float* gb0 = &g_gbaseT[(size_t)(r0 + 0) * NB + b0];
    const float* gb1 = &g_gbaseT[(size_t)(r0 + 1) * NB + b0];

    for (int t = 0; t < NTT; t++) {
        const float* hT = g_hbuf + (size_t)t * NH * NB;
        float* hTn = g_hbuf + (size_t)(t + 1) * NH * NB;
        const float* ge0 = &g_gembT[(size_t)(r0 + 0) * (NTT * NB) + t * NB + b0];
        const float* ge1 = &g_gembT[(size_t)(r0 + 1) * (NTT * NB) + t * NB + b0];
        float a00 = gb0[0] + ge0[0], a01 = gb0[1] + ge0[1];
        float a10 = gb1[0] + ge1[0], a11 = gb1[1] + ge1[1];
        #pragma unroll 8
        for (int k = 0; k < NH; k++) {
            float2 hv = *(const float2*)&hT[k * NB + b0];
            float w0 = W_s[lr0][k];
            float w1 = W_s[lr0 + 1][k];
            a00 = fmaf(w0, hv.x, a00); a01 = fmaf(w0, hv.y, a01);
            a10 = fmaf(w1, hv.x, a10); a11 = fmaf(w1, hv.y, a11);
        }
        gates_s[lr0][b0] = a00; gates_s[lr0][b0 + 1] = a01;
        gates_s[lr0 + 1][b0] = a10; gates_s[lr0 + 1][b0 + 1] = a11;
        __syncthreads();

        // LSTM cell for (hh, bb)
        float xi = gates_s[0 + hs][bb];
        float xf = gates_s[2 + hs][bb];
        float xg = gates_s[4 + hs][bb];
        float xo = gates_s[6 + hs][bb];
        float i_ = 1.f / (1.f + expf(-xi));
        float f_ = 1.f / (1.f + expf(-xf));
        float gg = tanhf(xg);
        float o_ = 1.f / (1.f + expf(-xo));
        c_reg = f_ * c_reg + i_ * gg;
        float hn = o_ * tanhf(c_reg);
        hTn[hh * NB + bb] = hn;
        Hall[(size_t)(t * NB + bb) * NH + hh] = hn;

        // grid-wide barrier (release: fence+atomic; acquire: spin+fence)
        __syncthreads();
        if (tid == 0) {
            __threadfence();
            atomicAdd(&g_bar, 1u);
            if (t < NTT - 1) {
                unsigned tgt = (unsigned)((t + 1) * NCTA);
                volatile unsigned* vb = &g_bar;
                while (*vb < tgt) {}
                __threadfence();
            }
        }
        __syncthreads();
    }
}

// ---------------- fc: tf32 tensor-core GEMM ---------------------------------
// out[(b*T+t)][v] = Hall[(t*B+b)][:] @ fc_W + fc_b
// M=4096, N=32000, K=256. BM=BN=128, BK=16, 256 thr (8 warps, 2x4),
// warp tile 64x32 via m16n8k8 (4x4 mma tiles), double-buffered smem.
// Bs pad = 136 (136 mod 32 = 8 -> tig*8+g covers 0..31: conflict-free).
__global__ void __launch_bounds__(256) fc_tf32_kernel(const float* __restrict__ A,
                                                      const float* __restrict__ Bw,
                                                      const float* __restrict__ bias,
                                                      float* __restrict__ out) {
    __shared__ uint32_t As[2][128 * 20];   // [m][k] pad 16->20
    __shared__ uint32_t Bs[2][16 * 136];   // [k][n] pad 128->136
    const int tid = threadIdx.x;
    const int m0 = blockIdx.y * 128, n0 = blockIdx.x * 128;
    const int lane = tid & 31, warp = tid >> 5;
    const int wm = (warp >> 2) * 64, wn = (warp & 3) * 32;
    const int g = lane >> 2, tig = lane & 3;
    const int a_row = tid >> 2, a_col = (tid & 3) * 4;
    const int b_row = tid >> 5, b_col = (tid & 31) * 4;
    const float* Ag = A + (size_t)(m0 + a_row) * NH + a_col;
    const float* Bg = Bw + (size_t)b_row * NV + n0 + b_col;

    float acc[4][4][4];
    #pragma unroll
    for (int i = 0; i < 4; i++)
        #pragma unroll
        for (int j = 0; j < 4; j++)
            #pragma unroll
            for (int r = 0; r < 4; r++) acc[i][j][r] = 0.f;

    float4 pa[2], pb[2];
    pa[0] = *(const float4*)(Ag);
    pa[1] = *(const float4*)(Ag + (size_t)64 * NH);
    pb[0] = *(const float4*)(Bg);
    pb[1] = *(const float4*)(Bg + (size_t)8 * NV);
    {
        uint32_t* d0 = &As[0][a_row * 20 + a_col];
        d0[0] = f2tf32(pa[0].x); d0[1] = f2tf32(pa[0].y);
        d0[2] = f2tf32(pa[0].z); d0[3] = f2tf32(pa[0].w);
        uint32_t* d1 = &As[0][(a_row + 64) * 20 + a_col];
        d1[0] = f2tf32(pa[1].x); d1[1] = f2tf32(pa[1].y);
        d1[2] = f2tf32(pa[1].z); d1[3] = f2tf32(pa[1].w);
        uint32_t* e0 = &Bs[0][b_row * 136 + b_col];
        e0[0] = f2tf32(pb[0].x); e0[1] = f2tf32(pb[0].y);
        e0[2] = f2tf32(pb[0].z); e0[3] = f2tf32(pb[0].w);
        uint32_t* e1 = &Bs[0][(b_row + 8) * 136 + b_col];
        e1[0] = f2tf32(pb[1].x); e1[1] = f2tf32(pb[1].y);
        e1[2] = f2tf32(pb[1].z); e1[3] = f2tf32(pb[1].w);
    }
    __syncthreads();

    #pragma unroll 1
    for (int it = 0; it < 16; it++) {
        const int cur = it & 1;
        if (it < 15) {
            const int k0 = (it + 1) * 16;
            pa[0] = *(const float4*)(Ag + k0);
            pa[1] = *(const float4*)(Ag + (size_t)64 * NH + k0);
            pb[0] = *(const float4*)(Bg + (size_t)k0 * NV);
            pb[1] = *(const float4*)(Bg + (size_t)(k0 + 8) * NV);
        }
        #pragma unroll
        for (int kk = 0; kk < 2; kk++) {
            uint32_t af[4][4], bf[4][2];
            #pragma unroll
            for (int ti = 0; ti < 4; ti++) {
                int r = wm + ti * 16 + g;
                af[ti][0] = As[cur][r * 20 + kk * 8 + tig];
                af[ti][1] = As[cur][(r + 8) * 20 + kk * 8 + tig];
                af[ti][2] = As[cur][r * 20 + kk * 8 + tig + 4];
                af[ti][3] = As[cur][(r + 8) * 20 + kk * 8 + tig + 4];
            }
            #pragma unroll
            for (int tj = 0; tj < 4; tj++) {
                int cb = wn + tj * 8 + g;
                bf[tj][0] = Bs[cur][(kk * 8 + tig) * 136 + cb];
                bf[tj][1] = Bs[cur][(kk * 8 + tig + 4) * 136 + cb];
            }
            #pragma unroll
            for (int ti = 0; ti < 4; ti++)
                #pragma unroll
                for (int tj = 0; tj < 4; tj++)
                    mma_tf32(acc[ti][tj], af[ti], bf[tj]);
        }
        if (it < 15) {
            const int nb = cur ^ 1;
            uint32_t* d0 = &As[nb][a_row * 20 + a_col];
            d0[0] = f2tf32(pa[0].x); d0[1] = f2tf32(pa[0].y);
            d0[2] = f2tf32(pa[0].z); d0[3] = f2tf32(pa[0].w);
            uint32_t* d1 = &As[nb][(a_row + 64) * 20 + a_col];
            d1[0] = f2tf32(pa[1].x); d1[1] = f2tf32(pa[1].y);
            d1[2] = f2tf32(pa[1].z); d1[3] = f2tf32(pa[1].w);
            uint32_t* e0 = &Bs[nb][b_row * 136 + b_col];
            e0[0] = f2tf32(pb[0].x); e0[1] = f2tf32(pb[0].y);
            e0[2] = f2tf32(pb[0].z); e0[3] = f2tf32(pb[0].w);
            uint32_t* e1 = &Bs[nb][(b_row + 8) * 136 + b_col];
            e1[0] = f2tf32(pb[1].x); e1[1] = f2tf32(pb[1].y);
            e1[2] = f2tf32(pb[1].z); e1[3] = f2tf32(pb[1].w);
        }
        __syncthreads();
    }

    // epilogue: row m = t*128 + b  ->  out row (b*NTT + t)
    #pragma unroll
    for (int ti = 0; ti < 4; ti++) {
        int mA = m0 + wm + ti * 16 + g;
        int mB = mA + 8;
        int tA = mA >> 7, bA = mA & 127;
        int tB = mB >> 7, bB = mB & 127;
        float* oA = out + (size_t)(bA * NTT + tA) * NV;
        float* oB = out + (size_t)(bB * NTT + tB) * NV;
        #pragma unroll
        for (int tj = 0; tj < 4; tj++) {
            int n = n0 + wn + tj * 8 + 2 * tig;
            float b0 = bias[n], b1 = bias[n + 1];
            float2 vA, vB;
            vA.x = acc[ti][tj][0] + b0; vA.y = acc[ti][tj][1] + b1;
            vB.x = acc[ti][tj][2] + b0; vB.y = acc[ti][tj][3] + b1;
            *(float2*)&oA[n] = vA;
            *(float2*)&oB[n] = vB;
        }
    }
}

// ---------------- launch ----------------------------------------------------
extern "C" void kernel_launch(void* const* d_in, const int* in_sizes, int n_in,
                              void* d_out, int out_size) {
    const float* features   = (const float*)d_in[0];
    const int*   captions   = (const int*)d_in[1];
    const float* embeddings = (const float*)d_in[2];
    const float* W_ih       = (const float*)d_in[3];
    const float* b_ih       = (const float*)d_in[4];
    const float* W_hh       = (const float*)d_in[5];
    const float* b_hh       = (const float*)d_in[6];
    const float* fc_W       = (const float*)d_in[7];
    const float* fc_b       = (const float*)d_in[8];
    // d_in[9..14] = attention weights: provably unused (softmax over length-1 axis == 1)
    const float* initH_W    = (const float*)d_in[15];
    const float* initH_b    = (const float*)d_in[16];
    const float* initC_W    = (const float*)d_in[17];
    const float* initC_b    = (const float*)d_in[18];
    float* out = (float*)d_out;

    void *p_embed_, *p_gembT_, *p_Hall_;
    cudaGetSymbolAddress(&p_embed_, g_embed);
    cudaGetSymbolAddress(&p_gembT_, g_gembT);
    cudaGetSymbolAddress(&p_Hall_,  g_Hall);
    float* p_embed = (float*)p_embed_;
    float* p_gembT = (float*)p_gembT_;
    float* p_Hall  = (float*)p_Hall_;

    // 1) gather word embeddings
    gather_embed_kernel<<<(NTT * NB * NE + 255) / 256, 256>>>(captions, embeddings);

    // 2) gates_emb transposed: gembT[j][(t*NB+b)] = W_ih[j,:E] . embed[t,b,:]
    //    M=1024 (j), N=4096 (t*b), K=128
    sgemm_nt64<<<dim3((NTT * NB) / 64, NG / 64), 256>>>(
        W_ih, LDW, p_embed, NE, p_gembT, NTT * NB, NE);

    // 3) gates_base transposed, K-split: gbaseT[j][b] = W_ih[j,E:] . feat[b] + b_ih[j] + b_hh[j]
    gbase_part_kernel<<<dim3(NB / 64, NG / 64, 8), 256>>>(W_ih + NE, features);
    gbase_reduce_kernel<<<(NG * NB) / 256, 256>>>(b_ih, b_hh);

    // 4) h0, c0 via K-split GEMM + deterministic transpose-reduce
    init_part_kernel<<<dim3(NH / 64, NB / 64, 8), 256>>>(features, initH_W, 0);
    init_part_kernel<<<dim3(NH / 64, NB / 64, 8), 256>>>(features, initC_W, 1);
    init_reduce_kernel<<<NB, NH>>>(initH_b, initC_b);

    // 5) fused persistent LSTM recurrence (single launch, grid barrier per step)
    reset_bar_kernel<<<1, 1>>>();
    lstm_persist_kernel<<<NCTA, 256>>>(W_hh, p_Hall);

    // 6) fc projection: tf32 tensor-core GEMM (4096, 256) @ (256, 32000)
    fc_tf32_kernel<<<dim3(NV / 128, (NTT * NB) / 128), 256>>>(p_Hall, fc_W, fc_b, out);
}

// round 10
// speedup vs baseline: 1.5585x; 1.5585x over previous
#include <cuda_runtime.h>
#include <stdint.h>
#include <math.h>

#define NB 128      // batch
#define NTT 32      // timesteps
#define NV 32000    // vocab
#define NE 128      // embed dim
#define NH 256      // hidden
#define NF 2048     // feature dim
#define NG 1024     // 4*H (gates)
#define LDW (NE + NF)   // W_ih row stride = 2176

// ---------------- scratch (device globals; no allocation allowed) ------------
__device__ float g_embed[NTT * NB * NE];       // [t][b][e]
__device__ float g_gates_emb[NTT * NB * NG];   // [t][b][j]
__device__ float g_gbase[NB * NG];             // [b][j] (+biases folded in)
__device__ float g_bpart[8 * NG * NB];         // K-split partials for gates_base ([j][b])
__device__ float g_gates[NB * NG];             // per-step gates
__device__ float g_h[NB * NH];
__device__ float g_c[NB * NH];
__device__ float g_Hall[NTT * NB * NH];        // [t][b][h]
__device__ float g_initpart[2 * 8 * NB * NH];  // K-split partials for h0/c0 ([b][h])

// ---------------- helpers ----------------------------------------------------
__device__ __forceinline__ uint32_t f2tf32(float x) {
    uint32_t u;
    asm("cvt.rna.tf32.f32 %0, %1;" : "=r"(u) : "f"(x));
    return u;
}

__device__ __forceinline__ void mma_tf32(float* d, const uint32_t* a, const uint32_t* b) {
    asm volatile(
        "mma.sync.aligned.m16n8k8.row.col.f32.tf32.tf32.f32 "
        "{%0,%1,%2,%3}, {%4,%5,%6,%7}, {%8,%9}, {%0,%1,%2,%3};"
        : "+f"(d[0]), "+f"(d[1]), "+f"(d[2]), "+f"(d[3])
        : "r"(a[0]), "r"(a[1]), "r"(a[2]), "r"(a[3]), "r"(b[0]), "r"(b[1]));
}

// ---------------- gather: g_embed[(t*NB+b)*NE + e] = embeddings[captions[b,t]] ----
__global__ void gather_embed_kernel(const int* __restrict__ captions,
                                    const float* __restrict__ embeddings) {
    int idx = blockIdx.x * blockDim.x + threadIdx.x;
    if (idx >= NTT * NB * NE) return;
    int e = idx % NE;
    int m = idx / NE;          // t*NB + b
    int t = m / NB;
    int b = m % NB;
    int tok = captions[b * NTT + t];
    g_embed[idx] = embeddings[tok * NE + e];
}

// ---------------- init h0/c0: NN gemm with deterministic K-split -------------
__global__ void init_part_kernel(const float* __restrict__ A,   // features (NB, NF)
                                 const float* __restrict__ W,   // (NF, NH)
                                 int mat) {
    __shared__ float As[16][64];
    __shared__ float Bs[16][64];
    int n0 = blockIdx.x * 64;
    int m0 = blockIdx.y * 64;
    int kz = blockIdx.z;
    int tid = threadIdx.x;
    int lm = tid >> 2, lk = (tid & 3) * 4;
    int kr = tid >> 4, n4 = (tid & 15) * 4;
    int tx = tid & 15, ty = tid >> 4;
    float acc[4][4] = {};

    for (int k0 = kz * 256; k0 < kz * 256 + 256; k0 += 16) {
        float4 av = *(const float4*)&A[(size_t)(m0 + lm) * NF + k0 + lk];
        As[lk + 0][lm] = av.x; As[lk + 1][lm] = av.y;
        As[lk + 2][lm] = av.z; As[lk + 3][lm] = av.w;
        float4 bv = *(const float4*)&W[(size_t)(k0 + kr) * NH + n0 + n4];
        *(float4*)&Bs[kr][n4] = bv;
        __syncthreads();
        #pragma unroll
        for (int kk = 0; kk < 16; kk++) {
            float4 a = *(const float4*)&As[kk][ty * 4];
            float4 b = *(const float4*)&Bs[kk][tx * 4];
            float ar[4] = {a.x, a.y, a.z, a.w};
            float br[4] = {b.x, b.y, b.z, b.w};
            #pragma unroll
            for (int i = 0; i < 4; i++)
                #pragma unroll
                for (int j = 0; j < 4; j++)
                    acc[i][j] = fmaf(ar[i], br[j], acc[i][j]);
        }
        __syncthreads();
    }
    float* dst = g_initpart + ((size_t)(mat * 8 + kz) * NB) * NH;
    #pragma unroll
    for (int i = 0; i < 4; i++)
        #pragma unroll
        for (int j = 0; j < 4; j++)
            dst[(size_t)(m0 + ty * 4 + i) * NH + n0 + tx * 4 + j] = acc[i][j];
}

__global__ void init_reduce_kernel(const float* __restrict__ bH,
                                   const float* __restrict__ bC) {
    int idx = blockIdx.x * blockDim.x + threadIdx.x;   // NB*NH, partials [b][h]
    int h = idx & 255;
    float sH = bH[h], sC = bC[h];
    #pragma unroll
    for (int z = 0; z < 8; z++) {
        sH += g_initpart[(size_t)z * NB * NH + idx];
        sC += g_initpart[(size_t)(8 + z) * NB * NH + idx];
    }
    g_h[idx] = sH;
    g_c[idx] = sC;
}

// ---------------- generic NT sgemm: C[M,N] = A(M,K) @ B(N,K)^T (+adds) -------
__global__ void sgemm_nt64(const float* __restrict__ A, int lda,
                           const float* __restrict__ B, int ldb,
                           float* __restrict__ C, int ldc, int K,
                           const float* __restrict__ add1,
                           const float* __restrict__ add2) {
    __shared__ float As[16][64];
    __shared__ float Bs[16][64];
    int m0 = blockIdx.y * 64;
    int n0 = blockIdx.x * 64;
    int tid = threadIdx.x;
    int lm = tid >> 2;
    int lk = (tid & 3) * 4;
    int tx = tid & 15;
    int ty = tid >> 4;
    float acc[4][4] = {};

    for (int k0 = 0; k0 < K; k0 += 16) {
        float4 av = *(const float4*)&A[(size_t)(m0 + lm) * lda + k0 + lk];
        float4 bv = *(const float4*)&B[(size_t)(n0 + lm) * ldb + k0 + lk];
        As[lk + 0][lm] = av.x; As[lk + 1][lm] = av.y;
        As[lk + 2][lm] = av.z; As[lk + 3][lm] = av.w;
        Bs[lk + 0][lm] = bv.x; Bs[lk + 1][lm] = bv.y;
        Bs[lk + 2][lm] = bv.z; Bs[lk + 3][lm] = bv.w;
        __syncthreads();
        #pragma unroll
        for (int kk = 0; kk < 16; kk++) {
            float4 a = *(const float4*)&As[kk][ty * 4];
            float4 b = *(const float4*)&Bs[kk][tx * 4];
            float ar[4] = {a.x, a.y, a.z, a.w};
            float br[4] = {b.x, b.y, b.z, b.w};
            #pragma unroll
            for (int i = 0; i < 4; i++)
                #pragma unroll
                for (int j = 0; j < 4; j++)
                    acc[i][j] = fmaf(ar[i], br[j], acc[i][j]);
        }
        __syncthreads();
    }

    #pragma unroll
    for (int i = 0; i < 4; i++) {
        int m = m0 + ty * 4 + i;
        #pragma unroll
        for (int j = 0; j < 4; j++) {
            int n = n0 + tx * 4 + j;
            float v = acc[i][j];
            if (add1) v += add1[(size_t)m * ldc + n];
            if (add2) v += add2[(size_t)m * ldc + n];
            C[(size_t)m * ldc + n] = v;
        }
    }
}

// ---------------- gates_base: K-split NT gemm (M=NG j-rows, N=NB, K=2048) ----
__global__ void gbase_part_kernel(const float* __restrict__ A,   // W_ih + NE, lda=LDW
                                  const float* __restrict__ B) { // features, ldb=NF
    __shared__ float As[16][64];
    __shared__ float Bs[16][64];
    int n0 = blockIdx.x * 64;   // b
    int m0 = blockIdx.y * 64;   // j
    int kz = blockIdx.z;
    int tid = threadIdx.x;
    int lm = tid >> 2;
    int lk = (tid & 3) * 4;
    int tx = tid & 15;
    int ty = tid >> 4;
    float acc[4][4] = {};

    for (int k0 = kz * 256; k0 < kz * 256 + 256; k0 += 16) {
        float4 av = *(const float4*)&A[(size_t)(m0 + lm) * LDW + k0 + lk];
        float4 bv = *(const float4*)&B[(size_t)(n0 + lm) * NF + k0 + lk];
        As[lk + 0][lm] = av.x; As[lk + 1][lm] = av.y;
        As[lk + 2][lm] = av.z; As[lk + 3][lm] = av.w;
        Bs[lk + 0][lm] = bv.x; Bs[lk + 1][lm] = bv.y;
        Bs[lk + 2][lm] = bv.z; Bs[lk + 3][lm] = bv.w;
        __syncthreads();
        #pragma unroll
        for (int kk = 0; kk < 16; kk++) {
            float4 a = *(const float4*)&As[kk][ty * 4];
            float4 b = *(const float4*)&Bs[kk][tx * 4];
            float ar[4] = {a.x, a.y, a.z, a.w};
            float br[4] = {b.x, b.y, b.z, b.w};
            #pragma unroll
            for (int i = 0; i < 4; i++)
                #pragma unroll
                for (int j = 0; j < 4; j++)
                    acc[i][j] = fmaf(ar[i], br[j], acc[i][j]);
        }
        __syncthreads();
    }
    float* dst = g_bpart + (size_t)kz * NG * NB;
    #pragma unroll
    for (int i = 0; i < 4; i++)
        #pragma unroll
        for (int j = 0; j < 4; j++)
            dst[(size_t)(m0 + ty * 4 + i) * NB + n0 + tx * 4 + j] = acc[i][j];
}

// reduce partials [j][b] -> g_gbase [b][j], folding both biases
__global__ void gbase_reduce_kernel(const float* __restrict__ bih,
                                    const float* __restrict__ bhh) {
    int idx = blockIdx.x * blockDim.x + threadIdx.x;   // over NG*NB, [j][b]
    int j = idx >> 7;
    int b = idx & 127;
    float s = bih[j] + bhh[j];
    #pragma unroll
    for (int z = 0; z < 8; z++)
        s += g_bpart[(size_t)z * NG * NB + idx];
    g_gbase[(size_t)b * NG + j] = s;
}

// ---------------- LSTM elementwise cell -------------------------------------
__global__ void lstm_cell_kernel(int t) {
    int idx = blockIdx.x * blockDim.x + threadIdx.x;   // 128*256
    int b = idx >> 8;
    int h = idx & 255;
    const float* g = g_gates + b * NG;
    float xi = g[h];
    float xf = g[256 + h];
    float xg = g[512 + h];
    float xo = g[768 + h];
    float i_ = 1.f / (1.f + expf(-xi));
    float f_ = 1.f / (1.f + expf(-xf));
    float gg = tanhf(xg);
    float o_ = 1.f / (1.f + expf(-xo));
    float c = f_ * g_c[idx] + i_ * gg;
    float hn = o_ * tanhf(c);
    g_c[idx] = c;
    g_h[idx] = hn;
    g_Hall[t * NB * NH + idx] = hn;
}

// ---------------- fc: tf32 tensor-core GEMM, fragment-major smem -------------
// out[(b*T+t)][v] = Hall[(t*B+b)][:] @ fc_W + fc_b
// M=4096, N=32000, K=256. BM=BN=128, BK=16, 8 warps (2x4), warp 64x32,
// m16n8k8, double-buffered. Smem holds tiles PRE-PERMUTED into fragment order:
//   A chunk (mb,kk): 32 lanes x 4 regs  -> one LDS.128 per fragment
//   B chunk (nb,kk): 32 lanes x 2 regs  -> one LDS.64  per fragment
__global__ void __launch_bounds__(256) fc_tf32_kernel(const float* __restrict__ A,
                                                      const float* __restrict__ Bw,
                                                      const float* __restrict__ bias,
                                                      float* __restrict__ out) {
    __shared__ __align__(16) uint32_t As[2][16 * 132];  // 16 chunks (mb*2+kk), pad 128->132
    __shared__ __align__(16) uint32_t Bs[2][32 * 66];   // 32 chunks (nb*2+kk), pad 64->66
    const int tid = threadIdx.x;
    const int m0 = blockIdx.y * 128, n0 = blockIdx.x * 128;
    const int lane = tid & 31, warp = tid >> 5;
    const int g = lane >> 2, tig = lane & 3;
    const int amb0 = (warp >> 2) * 4;      // A chunk row base (+ti)
    const int bnb0 = (warp & 3) * 4;       // B chunk row base (+tj)
    const int wm = (warp >> 2) * 64, wn = (warp & 3) * 32;

    // global load mapping (same as before)
    const int a_row = tid >> 2;            // 0..63 (and +64)
    const int a_col = (tid & 3) * 4;       // 0,4,8,12
    const int b_row = tid >> 5;            // 0..7 (and +8)
    const int b_col = (tid & 31) * 4;
    const float* Ag = A + (size_t)(m0 + a_row) * NH + a_col;
    const float* Bg = Bw + (size_t)b_row * NV + n0 + b_col;

    // writer scatter bases (fragment-major)
    const int a_mb = a_row >> 4;
    const int a_g = a_row & 7;
    const int a_half = (a_row >> 3) & 1;
    const int a_kk = a_col >> 3;
    const int a_chi = (a_col >> 2) & 1;
    const int a_reg = a_half + 2 * a_chi;
    const int aw0 = (a_mb * 2 + a_kk) * 132 + a_g * 16 + a_reg;        // element e: +4e
    const int aw1 = ((a_mb + 4) * 2 + a_kk) * 132 + a_g * 16 + a_reg;  // row + 64
    const int b_nb = b_col >> 3;
    const int b_g0 = b_col & 7;            // 0 or 4
    const int b_tig = b_row & 3;
    const int b_khi = (b_row >> 2) & 1;
    const int bw0 = (b_nb * 2 + 0) * 66 + (b_g0 * 4 + b_tig) * 2 + b_khi;  // element e: +8e
    const int bw1 = (b_nb * 2 + 1) * 66 + (b_g0 * 4 + b_tig) * 2 + b_khi;  // k + 8 -> kk=1

    float acc[4][4][4];
    #pragma unroll
    for (int i = 0; i < 4; i++)
        #pragma unroll
        for (int j = 0; j < 4; j++)
            #pragma unroll
            for (int r = 0; r < 4; r++) acc[i][j][r] = 0.f;

    float4 pa[2], pb[2];
    pa[0] = *(const float4*)(Ag);
    pa[1] = *(const float4*)(Ag + (size_t)64 * NH);
    pb[0] = *(const float4*)(Bg);
    pb[1] = *(const float4*)(Bg + (size_t)8 * NV);
    {
        As[0][aw0] = f2tf32(pa[0].x); As[0][aw0 + 4] = f2tf32(pa[0].y);
        As[0][aw0 + 8] = f2tf32(pa[0].z); As[0][aw0 + 12] = f2tf32(pa[0].w);
        As[0][aw1] = f2tf32(pa[1].x); As[0][aw1 + 4] = f2tf32(pa[1].y);
        As[0][aw1 + 8] = f2tf32(pa[1].z); As[0][aw1 + 12] = f2tf32(pa[1].w);
        Bs[0][bw0] = f2tf32(pb[0].x); Bs[0][bw0 + 8] = f2tf32(pb[0].y);
        Bs[0][bw0 + 16] = f2tf32(pb[0].z); Bs[0][bw0 + 24] = f2tf32(pb[0].w);
        Bs[0][bw1] = f2tf32(pb[1].x); Bs[0][bw1 + 8] = f2tf32(pb[1].y);
        Bs[0][bw1 + 16] = f2tf32(pb[1].z); Bs[0][bw1 + 24] = f2tf32(pb[1].w);
    }
    __syncthreads();

    #pragma unroll 1
    for (int it = 0; it < 16; it++) {
        const int cur = it & 1;
        if (it < 15) {
            const int k0 = (it + 1) * 16;
            pa[0] = *(const float4*)(Ag + k0);
            pa[1] = *(const float4*)(Ag + (size_t)64 * NH + k0);
            pb[0] = *(const float4*)(Bg + (size_t)k0 * NV);
            pb[1] = *(const float4*)(Bg + (size_t)(k0 + 8) * NV);
        }
        #pragma unroll
        for (int kk = 0; kk < 2; kk++) {
            uint4 af[4];
            uint2 bf[4];
            #pragma unroll
            for (int ti = 0; ti < 4; ti++)
                af[ti] = *(const uint4*)&As[cur][((amb0 + ti) * 2 + kk) * 132 + lane * 4];
            #pragma unroll
            for (int tj = 0; tj < 4; tj++)
                bf[tj] = *(const uint2*)&Bs[cur][((bnb0 + tj) * 2 + kk) * 66 + lane * 2];
            #pragma unroll
            for (int ti = 0; ti < 4; ti++)
                #pragma unroll
                for (int tj = 0; tj < 4; tj++)
                    mma_tf32(acc[ti][tj],
                             reinterpret_cast<const uint32_t*>(&af[ti]),
                             reinterpret_cast<const uint32_t*>(&bf[tj]));
        }
        if (it < 15) {
            const int nb = cur ^ 1;
            As[nb][aw0] = f2tf32(pa[0].x); As[nb][aw0 + 4] = f2tf32(pa[0].y);
            As[nb][aw0 + 8] = f2tf32(pa[0].z); As[nb][aw0 + 12] = f2tf32(pa[0].w);
            As[nb][aw1] = f2tf32(pa[1].x); As[nb][aw1 + 4] = f2tf32(pa[1].y);
            As[nb][aw1 + 8] = f2tf32(pa[1].z); As[nb][aw1 + 12] = f2tf32(pa[1].w);
            Bs[nb][bw0] = f2tf32(pb[0].x); Bs[nb][bw0 + 8] = f2tf32(pb[0].y);
            Bs[nb][bw0 + 16] = f2tf32(pb[0].z); Bs[nb][bw0 + 24] = f2tf32(pb[0].w);
            Bs[nb][bw1] = f2tf32(pb[1].x); Bs[nb][bw1 + 8] = f2tf32(pb[1].y);
            Bs[nb][bw1 + 16] = f2tf32(pb[1].z); Bs[nb][bw1 + 24] = f2tf32(pb[1].w);
        }
        __syncthreads();
    }

    // epilogue: row m = t*128 + b  ->  out row (b*NTT + t)
    #pragma unroll
    for (int ti = 0; ti < 4; ti++) {
        int mA = m0 + wm + ti * 16 + g;
        int mB = mA + 8;
        int tA = mA >> 7, bA = mA & 127;
        int tB = mB >> 7, bB = mB & 127;
        float* oA = out + (size_t)(bA * NTT + tA) * NV;
        float* oB = out + (size_t)(bB * NTT + tB) * NV;
        #pragma unroll
        for (int tj = 0; tj < 4; tj++) {
            int n = n0 + wn + tj * 8 + 2 * tig;
            float b0 = bias[n], b1 = bias[n + 1];
            float2 vA, vB;
            vA.x = acc[ti][tj][0] + b0; vA.y = acc[ti][tj][1] + b1;
            vB.x = acc[ti][tj][2] + b0; vB.y = acc[ti][tj][3] + b1;
            *(float2*)&oA[n] = vA;
            *(float2*)&oB[n] = vB;
        }
    }
}

// ---------------- launch ----------------------------------------------------
extern "C" void kernel_launch(void* const* d_in, const int* in_sizes, int n_in,
                              void* d_out, int out_size) {
    const float* features   = (const float*)d_in[0];
    const int*   captions   = (const int*)d_in[1];
    const float* embeddings = (const float*)d_in[2];
    const float* W_ih       = (const float*)d_in[3];
    const float* b_ih       = (const float*)d_in[4];
    const float* W_hh       = (const float*)d_in[5];
    const float* b_hh       = (const float*)d_in[6];
    const float* fc_W       = (const float*)d_in[7];
    const float* fc_b       = (const float*)d_in[8];
    // d_in[9..14] = attention weights: provably unused (softmax over length-1 axis == 1)
    const float* initH_W    = (const float*)d_in[15];
    const float* initH_b    = (const float*)d_in[16];
    const float* initC_W    = (const float*)d_in[17];
    const float* initC_b    = (const float*)d_in[18];
    float* out = (float*)d_out;

    void *p_embed_, *p_gemb_, *p_gbase_, *p_gates_, *p_h_, *p_Hall_;
    cudaGetSymbolAddress(&p_embed_, g_embed);
    cudaGetSymbolAddress(&p_gemb_,  g_gates_emb);
    cudaGetSymbolAddress(&p_gbase_, g_gbase);
    cudaGetSymbolAddress(&p_gates_, g_gates);
    cudaGetSymbolAddress(&p_h_,     g_h);
    cudaGetSymbolAddress(&p_Hall_,  g_Hall);
    float* p_embed = (float*)p_embed_;
    float* p_gemb  = (float*)p_gemb_;
    float* p_gbase = (float*)p_gbase_;
    float* p_gates = (float*)p_gates_;
    float* p_h     = (float*)p_h_;
    float* p_Hall  = (float*)p_Hall_;

    // 1) gather word embeddings
    gather_embed_kernel<<<(NTT * NB * NE + 255) / 256, 256>>>(captions, embeddings);

    // 2) gates_emb[t,b,:] = embed @ W_ih[:, :E]^T   (M=4096, N=1024, K=128)
    sgemm_nt64<<<dim3(NG / 64, (NTT * NB) / 64), 256>>>(
        p_embed, NE, W_ih, LDW, p_gemb, NG, NE, nullptr, nullptr);

    // 3) gates_base: K-split GEMM + deterministic transpose-reduce (+biases)
    gbase_part_kernel<<<dim3(NB / 64, NG / 64, 8), 256>>>(W_ih + NE, features);
    gbase_reduce_kernel<<<(NG * NB) / 256, 256>>>(b_ih, b_hh);

    // 4) h0, c0 via K-split GEMM + deterministic reduce
    init_part_kernel<<<dim3(NH / 64, NB / 64, 8), 256>>>(features, initH_W, 0);
    init_part_kernel<<<dim3(NH / 64, NB / 64, 8), 256>>>(features, initC_W, 1);
    init_reduce_kernel<<<NB, NH>>>(initH_b, initC_b);

    // 5) sequential LSTM steps (known-good unfused loop)
    for (int t = 0; t < NTT; t++) {
        sgemm_nt64<<<dim3(NG / 64, NB / 64), 256>>>(
            p_h, NH, W_hh, NH, p_gates, NG, NH,
            p_gbase, p_gemb + (size_t)t * NB * NG);
        lstm_cell_kernel<<<NB, NH>>>(t);
    }

    // 6) fc projection: tf32 tensor-core GEMM (4096, 256) @ (256, 32000)
    fc_tf32_kernel<<<dim3(NV / 128, (NTT * NB) / 128), 256>>>(p_Hall, fc_W, fc_b, out);
}